// round 1
// baseline (speedup 1.0000x reference)
#include <cuda_runtime.h>
#include <math.h>

#define BB 64
#define SS 100
#define DIN 256
#define HH 512
#define DOUT 256
#define WR 16          // window radius
#define WIN 33
#define NBS (BB*SS)    // 6400
#define BAND 65        // 2*32+1 diagonals

// ---------------- scratch (no allocation allowed) ----------------
__device__ float g_h  [NBS*HH];
__device__ float g_q  [NBS*HH];
__device__ float g_k  [NBS*HH];
__device__ float g_v  [NBS*HH];
__device__ float g_G  [NBS*BAND];
__device__ float g_att[NBS*HH];

// ---------------- tiled fp32 GEMM: C = relu?(A@B + bias) ----------------
// A [M,K] row-major, B [K,N] row-major, C [M,N].
// BM=128 BN=64 BK=16, 256 threads, 8x4 per thread. M%128==0, N%64==0, K%16==0.
template<bool RELU, bool BIAS>
__global__ __launch_bounds__(256)
void sgemm_kernel(const float* __restrict__ A, const float* __restrict__ B,
                  const float* __restrict__ bias, float* __restrict__ C,
                  int M, int N, int K)
{
    const int BM = 128, BN = 64, BK = 16;
    __shared__ float As[BK * BM];   // transposed: As[k][m]
    __shared__ float Bs[BK * BN];   // Bs[k][n]

    int tid = threadIdx.x;
    int tx = tid & 15;      // 16 col groups (TN=4)
    int ty = tid >> 4;      // 16 row groups (TM=8)
    int bm = blockIdx.y * BM;
    int bn = blockIdx.x * BN;

    float acc[8][4];
#pragma unroll
    for (int i = 0; i < 8; i++)
#pragma unroll
        for (int j = 0; j < 4; j++) acc[i][j] = 0.f;

    for (int k0 = 0; k0 < K; k0 += BK) {
        // load A tile: 128x16 = 512 float4, 2 per thread
#pragma unroll
        for (int it = 0; it < 2; it++) {
            int f = tid + it * 256;       // [0,512)
            int row = f >> 2;             // [0,128)
            int cv  = f & 3;              // float4 index along K
            float4 a = *(const float4*)&A[(size_t)(bm + row) * K + k0 + cv * 4];
            As[(cv * 4 + 0) * BM + row] = a.x;
            As[(cv * 4 + 1) * BM + row] = a.y;
            As[(cv * 4 + 2) * BM + row] = a.z;
            As[(cv * 4 + 3) * BM + row] = a.w;
        }
        // load B tile: 16x64 = 256 float4, 1 per thread
        {
            int row = tid >> 4;           // [0,16)
            int cv  = tid & 15;           // [0,16) float4 along N
            float4 b = *(const float4*)&B[(size_t)(k0 + row) * N + bn + cv * 4];
            *(float4*)&Bs[row * BN + cv * 4] = b;
        }
        __syncthreads();

#pragma unroll
        for (int kk = 0; kk < BK; kk++) {
            float4 a0 = *(const float4*)&As[kk * BM + ty * 8 + 0];
            float4 a1 = *(const float4*)&As[kk * BM + ty * 8 + 4];
            float4 b0 = *(const float4*)&Bs[kk * BN + tx * 4];
            float ra[8] = {a0.x,a0.y,a0.z,a0.w,a1.x,a1.y,a1.z,a1.w};
            float rb[4] = {b0.x,b0.y,b0.z,b0.w};
#pragma unroll
            for (int i = 0; i < 8; i++)
#pragma unroll
                for (int j = 0; j < 4; j++)
                    acc[i][j] = fmaf(ra[i], rb[j], acc[i][j]);
        }
        __syncthreads();
    }

    int col = bn + tx * 4;
    float4 bv = {0,0,0,0};
    if (BIAS) bv = *(const float4*)&bias[col];
#pragma unroll
    for (int i = 0; i < 8; i++) {
        int row = bm + ty * 8 + i;
        float4 o;
        o.x = acc[i][0] + bv.x;
        o.y = acc[i][1] + bv.y;
        o.z = acc[i][2] + bv.z;
        o.w = acc[i][3] + bv.w;
        if (RELU) {
            o.x = fmaxf(o.x, 0.f); o.y = fmaxf(o.y, 0.f);
            o.z = fmaxf(o.z, 0.f); o.w = fmaxf(o.w, 0.f);
        }
        *(float4*)&C[(size_t)row * N + col] = o;
    }
}

// ---------------- banded Gram: G[b,p,j] = q[b,p] . k[b,p+j-32] ----------------
__global__ __launch_bounds__(256)
void band_kernel(const float* __restrict__ q, const float* __restrict__ k,
                 float* __restrict__ G)
{
    int bs = blockIdx.x;                  // b*S + p
    int b = bs / SS, p = bs % SS;
    __shared__ float qs[HH];
    for (int e = threadIdx.x; e < HH; e += 256) qs[e] = q[(size_t)bs * HH + e];
    __syncthreads();

    int warp = threadIdx.x >> 5, lane = threadIdx.x & 31;
    for (int j = warp; j < BAND; j += 8) {
        int pp = p + j - 32;
        float acc = 0.f;
        if (pp >= 0 && pp < SS) {
            const float* kr = k + (size_t)(b * SS + pp) * HH;
#pragma unroll 4
            for (int e = lane; e < HH; e += 32)
                acc = fmaf(qs[e], kr[e], acc);
#pragma unroll
            for (int o = 16; o; o >>= 1)
                acc += __shfl_xor_sync(0xffffffffu, acc, o);
        }
        if (lane == 0) G[(size_t)bs * BAND + j] = acc;
    }
}

// ---------------- softmax + beta + weighted V ----------------
// One block per (b,s). Writes alpha [33,33] to out, att row [512] to g_att.
__global__ __launch_bounds__(256)
void attn_kernel(const float* __restrict__ G, const float* __restrict__ v,
                 float* __restrict__ alpha_out, float* __restrict__ att)
{
    int bs = blockIdx.x;
    int b = bs / SS, s = bs % SS;
    __shared__ float dmat[WIN * WIN];
    __shared__ float beta[WIN];
    const float invs = 0.044194173824159216f;  // 1/sqrt(512)

    // build d matrix (zero-fill for padded neighbors, matching reference: exp(0) terms!)
    for (int idx = threadIdx.x; idx < WIN * WIN; idx += 256) {
        int w_ = idx / WIN, u = idx % WIN;
        int p  = s + WR - w_;
        int pu = s + WR - u;
        float val = 0.f;
        if (p >= 0 && p < SS && pu >= 0 && pu < SS)
            val = G[(size_t)(b * SS + p) * BAND + (w_ - u) + 32] * invs;
        dmat[idx] = val;
    }
    __syncthreads();

    // softmax per row (warp per row, 33 elements: lanes 0..31 + lane0 handles elem 32)
    int warp = threadIdx.x >> 5, lane = threadIdx.x & 31;
    for (int r = warp; r < WIN; r += 8) {
        float x0 = dmat[r * WIN + lane];
        float x1 = (lane == 0) ? dmat[r * WIN + 32] : -1e30f;
        float m = fmaxf(x0, x1);
#pragma unroll
        for (int o = 16; o; o >>= 1)
            m = fmaxf(m, __shfl_xor_sync(0xffffffffu, m, o));
        float e0 = __expf(x0 - m);
        float e1 = (lane == 0) ? __expf(x1 - m) : 0.f;
        float ssum = e0 + e1;
#pragma unroll
        for (int o = 16; o; o >>= 1)
            ssum += __shfl_xor_sync(0xffffffffu, ssum, o);
        float rinv = __frcp_rn(ssum);
        e0 *= rinv; e1 *= rinv;
        dmat[r * WIN + lane] = e0;
        if (lane == 0) dmat[r * WIN + 32] = e1;
        float* ao = alpha_out + (size_t)bs * (WIN * WIN) + r * WIN;
        ao[lane] = e0;
        if (lane == 0) ao[32] = e1;
    }
    __syncthreads();

    // beta[u] = sum over rows
    if (threadIdx.x < WIN) {
        float acc = 0.f;
        for (int r = 0; r < WIN; r++) acc += dmat[r * WIN + threadIdx.x];
        beta[threadIdx.x] = acc;
    }
    __syncthreads();

    // att[h] = sum_u beta[u] * v[b, s+16-u, h]
    int h2 = threadIdx.x * 2;
    float ax = 0.f, ay = 0.f;
#pragma unroll
    for (int u = 0; u < WIN; u++) {
        int pu = s + WR - u;
        if (pu >= 0 && pu < SS) {
            float bu = beta[u];
            float2 vr = *(const float2*)&v[(size_t)(b * SS + pu) * HH + h2];
            ax = fmaf(bu, vr.x, ax);
            ay = fmaf(bu, vr.y, ay);
        }
    }
    float2 o; o.x = ax; o.y = ay;
    *(float2*)&att[(size_t)bs * HH + h2] = o;
}

// ---------------- launch ----------------
extern "C" void kernel_launch(void* const* d_in, const int* in_sizes, int n_in,
                              void* d_out, int out_size)
{
    const float* x  = (const float*)d_in[0];
    const float* W0 = (const float*)d_in[1];
    const float* b0 = (const float*)d_in[2];
    const float* Wq = (const float*)d_in[3];
    const float* Wk = (const float*)d_in[4];
    const float* Wv = (const float*)d_in[5];
    const float* W1 = (const float*)d_in[6];
    const float* b1 = (const float*)d_in[7];
    float* out = (float*)d_out;
    float* y_out     = out;                       // [6400, 256]
    float* alpha_out = out + (size_t)NBS * DOUT;  // [6400, 33, 33]

    float *h, *q, *k, *v, *G, *att;
    cudaGetSymbolAddress((void**)&h,   g_h);
    cudaGetSymbolAddress((void**)&q,   g_q);
    cudaGetSymbolAddress((void**)&k,   g_k);
    cudaGetSymbolAddress((void**)&v,   g_v);
    cudaGetSymbolAddress((void**)&G,   g_G);
    cudaGetSymbolAddress((void**)&att, g_att);

    // h = relu(x @ W0 + b0)   [6400,256]@[256,512]
    {
        dim3 grid(HH / 64, NBS / 128);
        sgemm_kernel<true, true><<<grid, 256>>>(x, W0, b0, h, NBS, HH, DIN);
    }
    // q,k,v = h @ W{q,k,v}    [6400,512]@[512,512]
    {
        dim3 grid(HH / 64, NBS / 128);
        sgemm_kernel<false, false><<<grid, 256>>>(h, Wq, nullptr, q, NBS, HH, HH);
        sgemm_kernel<false, false><<<grid, 256>>>(h, Wk, nullptr, k, NBS, HH, HH);
        sgemm_kernel<false, false><<<grid, 256>>>(h, Wv, nullptr, v, NBS, HH, HH);
    }
    // banded gram
    band_kernel<<<NBS, 256>>>(q, k, G);
    // softmax + alpha + weighted V
    attn_kernel<<<NBS, 256>>>(G, v, alpha_out, att);
    // y = relu(att @ W1 + b1) [6400,512]@[512,256]
    {
        dim3 grid(DOUT / 64, NBS / 128);
        sgemm_kernel<true, true><<<grid, 256>>>(att, W1, b1, y_out, NBS, DOUT, HH);
    }
}

// round 2
// speedup vs baseline: 1.4452x; 1.4452x over previous
#include <cuda_runtime.h>
#include <math.h>

#define BB 64
#define SS 100
#define DIN 256
#define HH 512
#define DOUT 256
#define WR 16
#define WIN 33
#define NBS (BB*SS)

// ---------------- scratch ----------------
__device__ float g_h  [NBS*HH];
__device__ float g_q  [NBS*HH];
__device__ float g_k  [NBS*HH];
__device__ float g_v  [NBS*HH];
__device__ float g_G  [BB*SS*SS];
__device__ float g_att[NBS*HH];

__device__ __forceinline__ unsigned f2tf(float x){
    unsigned r; asm("cvt.rna.tf32.f32 %0, %1;" : "=r"(r) : "f"(x)); return r;
}
__device__ __forceinline__ void mma_tf32(float c[4], unsigned a0,unsigned a1,unsigned a2,unsigned a3,
                                         unsigned b0, unsigned b1){
    asm volatile("mma.sync.aligned.m16n8k8.row.col.f32.tf32.tf32.f32 "
        "{%0,%1,%2,%3},{%4,%5,%6,%7},{%8,%9},{%0,%1,%2,%3};"
        : "+f"(c[0]),"+f"(c[1]),"+f"(c[2]),"+f"(c[3])
        : "r"(a0),"r"(a1),"r"(a2),"r"(a3),"r"(b0),"r"(b1));
}

// ---------------- tf32 tensor-core GEMM: C = relu?(A@B + bias) ----------------
// A [M,K] rm, B [K,N] rm, C [M,N]. BM=128 BN=64 BK=32, 256 thr.
// Warp grid 4(M)x2(N), warp tile 32x32 = 2x4 m16n8 tiles.
template<bool RELU, bool BIAS>
__global__ __launch_bounds__(256)
void tgemm_kernel(const float* __restrict__ A, const float* __restrict__ B,
                  const float* __restrict__ bias, float* __restrict__ C,
                  int M, int N, int K)
{
    const int BM=128, BN=64, BK=32, SA=36, SB=72;
    __shared__ unsigned As[BM*SA];
    __shared__ unsigned Bs[BK*SB];
    int tid = threadIdx.x;
    int lane = tid & 31, w = tid >> 5;
    int wm = w & 3, wn = w >> 2;
    int g = lane >> 2, t = lane & 3;
    int bm = blockIdx.y * BM, bn = blockIdx.x * BN;

    float acc[2][4][4] = {};

    for (int k0 = 0; k0 < K; k0 += BK) {
        // A tile 128x32: 1024 float4
        #pragma unroll
        for (int i = 0; i < 4; i++) {
            int f = tid + i*256;
            int row = f >> 3, c4 = (f & 7) * 4;
            float4 v = *(const float4*)&A[(size_t)(bm+row)*K + k0 + c4];
            unsigned* d = &As[row*SA + c4];
            d[0]=f2tf(v.x); d[1]=f2tf(v.y); d[2]=f2tf(v.z); d[3]=f2tf(v.w);
        }
        // B tile 32x64: 512 float4
        #pragma unroll
        for (int i = 0; i < 2; i++) {
            int f = tid + i*256;
            int kk = f >> 4, c4 = (f & 15) * 4;
            float4 v = *(const float4*)&B[(size_t)(k0+kk)*N + bn + c4];
            unsigned* d = &Bs[kk*SB + c4];
            d[0]=f2tf(v.x); d[1]=f2tf(v.y); d[2]=f2tf(v.z); d[3]=f2tf(v.w);
        }
        __syncthreads();
        #pragma unroll
        for (int ks = 0; ks < 4; ks++) {
            unsigned a[2][4], b[4][2];
            #pragma unroll
            for (int mt = 0; mt < 2; mt++) {
                int m0 = wm*32 + mt*16;
                const unsigned* ap = &As[(m0+g)*SA + ks*8 + t];
                a[mt][0]=ap[0]; a[mt][1]=ap[8*SA]; a[mt][2]=ap[4]; a[mt][3]=ap[8*SA+4];
            }
            #pragma unroll
            for (int nt = 0; nt < 4; nt++) {
                int n0 = wn*32 + nt*8;
                const unsigned* bp = &Bs[(ks*8+t)*SB + n0 + g];
                b[nt][0]=bp[0]; b[nt][1]=bp[4*SB];
            }
            #pragma unroll
            for (int mt = 0; mt < 2; mt++)
                #pragma unroll
                for (int nt = 0; nt < 4; nt++)
                    mma_tf32(acc[mt][nt], a[mt][0],a[mt][1],a[mt][2],a[mt][3],
                             b[nt][0], b[nt][1]);
        }
        __syncthreads();
    }

    #pragma unroll
    for (int mt = 0; mt < 2; mt++) {
        int r0 = bm + wm*32 + mt*16 + g;
        #pragma unroll
        for (int nt = 0; nt < 4; nt++) {
            int col = bn + wn*32 + nt*8 + 2*t;
            float bx = 0.f, by = 0.f;
            if (BIAS) { bx = bias[col]; by = bias[col+1]; }
            float2 o0, o1;
            o0.x = acc[mt][nt][0] + bx; o0.y = acc[mt][nt][1] + by;
            o1.x = acc[mt][nt][2] + bx; o1.y = acc[mt][nt][3] + by;
            if (RELU) {
                o0.x=fmaxf(o0.x,0.f); o0.y=fmaxf(o0.y,0.f);
                o1.x=fmaxf(o1.x,0.f); o1.y=fmaxf(o1.y,0.f);
            }
            *(float2*)&C[(size_t)r0*N + col]     = o0;
            *(float2*)&C[(size_t)(r0+8)*N + col] = o1;
        }
    }
}

// ---------------- per-batch Gram: G[b,p,u] = (q[b,p].k[b,u]) / sqrt(H) ----------------
// One block per batch. M=N=100 padded to 128. Warp grid 2(M)x4(N), warp tile 64x32.
__global__ __launch_bounds__(256)
void gram_kernel(const float* __restrict__ q, const float* __restrict__ kmat,
                 float* __restrict__ G)
{
    const int BK=32, SA=36, SBg=129;
    __shared__ unsigned As[128*SA];
    __shared__ unsigned Bs[BK*SBg];
    int b = blockIdx.x;
    int tid = threadIdx.x, lane = tid & 31, w = tid >> 5;
    int wm = w & 1, wn = w >> 1;
    int g = lane >> 2, t = lane & 3;
    const float* qb = q    + (size_t)b*SS*HH;
    const float* kb = kmat + (size_t)b*SS*HH;
    float acc[4][4][4] = {};

    for (int k0 = 0; k0 < HH; k0 += BK) {
        #pragma unroll
        for (int i = 0; i < 4; i++) {
            int f = tid + i*256;
            int row = f >> 3, c4 = (f & 7) * 4;
            int sr = row < SS ? row : SS-1;
            float4 v = *(const float4*)&qb[(size_t)sr*HH + k0 + c4];
            unsigned* d = &As[row*SA + c4];
            d[0]=f2tf(v.x); d[1]=f2tf(v.y); d[2]=f2tf(v.z); d[3]=f2tf(v.w);
        }
        // transposed K tile: Bs[k][n] = kb[n][k]
        #pragma unroll
        for (int i = 0; i < 4; i++) {
            int f = tid + i*256;
            int n = f >> 3, c4 = (f & 7) * 4;
            int sn = n < SS ? n : SS-1;
            float4 v = *(const float4*)&kb[(size_t)sn*HH + k0 + c4];
            Bs[(c4+0)*SBg + n] = f2tf(v.x);
            Bs[(c4+1)*SBg + n] = f2tf(v.y);
            Bs[(c4+2)*SBg + n] = f2tf(v.z);
            Bs[(c4+3)*SBg + n] = f2tf(v.w);
        }
        __syncthreads();
        #pragma unroll
        for (int ks = 0; ks < 4; ks++) {
            unsigned a[4][4], bb[4][2];
            #pragma unroll
            for (int mt = 0; mt < 4; mt++) {
                int m0 = wm*64 + mt*16;
                const unsigned* ap = &As[(m0+g)*SA + ks*8 + t];
                a[mt][0]=ap[0]; a[mt][1]=ap[8*SA]; a[mt][2]=ap[4]; a[mt][3]=ap[8*SA+4];
            }
            #pragma unroll
            for (int nt = 0; nt < 4; nt++) {
                int n0 = wn*32 + nt*8;
                const unsigned* bp = &Bs[(ks*8+t)*SBg + n0 + g];
                bb[nt][0]=bp[0]; bb[nt][1]=bp[4*SBg];
            }
            #pragma unroll
            for (int mt = 0; mt < 4; mt++)
                #pragma unroll
                for (int nt = 0; nt < 4; nt++)
                    mma_tf32(acc[mt][nt], a[mt][0],a[mt][1],a[mt][2],a[mt][3],
                             bb[nt][0], bb[nt][1]);
        }
        __syncthreads();
    }

    const float invs = 0.044194173824159216f;  // 1/sqrt(512)
    float* Gb = G + (size_t)b*SS*SS;
    #pragma unroll
    for (int mt = 0; mt < 4; mt++) {
        int r0 = wm*64 + mt*16 + g;
        #pragma unroll
        for (int nt = 0; nt < 4; nt++) {
            int col = wn*32 + nt*8 + 2*t;
            if (col < SS) {
                if (r0 < SS) {
                    Gb[r0*SS + col]     = acc[mt][nt][0]*invs;
                    Gb[r0*SS + col + 1] = acc[mt][nt][1]*invs;
                }
                if (r0+8 < SS) {
                    Gb[(r0+8)*SS + col]     = acc[mt][nt][2]*invs;
                    Gb[(r0+8)*SS + col + 1] = acc[mt][nt][3]*invs;
                }
            }
        }
    }
}

// ---------------- softmax + beta + weighted V ----------------
__global__ __launch_bounds__(256)
void attn_kernel(const float* __restrict__ G, const float* __restrict__ v,
                 float* __restrict__ alpha_out, float* __restrict__ att)
{
    int bs = blockIdx.x;
    int b = bs / SS, s = bs % SS;
    __shared__ float dmat[WIN * WIN];
    __shared__ float beta[WIN];
    const float* Gb = G + (size_t)b*SS*SS;

    // build d matrix (zero-fill padded neighbors — matches unmasked reference)
    for (int idx = threadIdx.x; idx < WIN * WIN; idx += 256) {
        int w_ = idx / WIN, u = idx % WIN;
        int p  = s + WR - w_;
        int pu = s + WR - u;
        float val = 0.f;
        if (p >= 0 && p < SS && pu >= 0 && pu < SS)
            val = Gb[p*SS + pu];
        dmat[idx] = val;
    }
    __syncthreads();

    int warp = threadIdx.x >> 5, lane = threadIdx.x & 31;
    for (int r = warp; r < WIN; r += 8) {
        float x0 = dmat[r * WIN + lane];
        float x1 = (lane == 0) ? dmat[r * WIN + 32] : -1e30f;
        float m = fmaxf(x0, x1);
#pragma unroll
        for (int o = 16; o; o >>= 1)
            m = fmaxf(m, __shfl_xor_sync(0xffffffffu, m, o));
        float e0 = __expf(x0 - m);
        float e1 = (lane == 0) ? __expf(x1 - m) : 0.f;
        float ssum = e0 + e1;
#pragma unroll
        for (int o = 16; o; o >>= 1)
            ssum += __shfl_xor_sync(0xffffffffu, ssum, o);
        float rinv = __frcp_rn(ssum);
        e0 *= rinv; e1 *= rinv;
        dmat[r * WIN + lane] = e0;
        if (lane == 0) dmat[r * WIN + 32] = e1;
        float* ao = alpha_out + (size_t)bs * (WIN * WIN) + r * WIN;
        ao[lane] = e0;
        if (lane == 0) ao[32] = e1;
    }
    __syncthreads();

    if (threadIdx.x < WIN) {
        float acc = 0.f;
        for (int r = 0; r < WIN; r++) acc += dmat[r * WIN + threadIdx.x];
        beta[threadIdx.x] = acc;
    }
    __syncthreads();

    int h2 = threadIdx.x * 2;
    float ax = 0.f, ay = 0.f;
#pragma unroll
    for (int u = 0; u < WIN; u++) {
        int pu = s + WR - u;
        if (pu >= 0 && pu < SS) {
            float bu = beta[u];
            float2 vr = *(const float2*)&v[(size_t)(b * SS + pu) * HH + h2];
            ax = fmaf(bu, vr.x, ax);
            ay = fmaf(bu, vr.y, ay);
        }
    }
    float2 o; o.x = ax; o.y = ay;
    *(float2*)&att[(size_t)bs * HH + h2] = o;
}

// ---------------- launch ----------------
extern "C" void kernel_launch(void* const* d_in, const int* in_sizes, int n_in,
                              void* d_out, int out_size)
{
    const float* x  = (const float*)d_in[0];
    const float* W0 = (const float*)d_in[1];
    const float* b0 = (const float*)d_in[2];
    const float* Wq = (const float*)d_in[3];
    const float* Wk = (const float*)d_in[4];
    const float* Wv = (const float*)d_in[5];
    const float* W1 = (const float*)d_in[6];
    const float* b1 = (const float*)d_in[7];
    float* out = (float*)d_out;
    float* y_out     = out;
    float* alpha_out = out + (size_t)NBS * DOUT;

    float *h, *q, *k, *v, *G, *att;
    cudaGetSymbolAddress((void**)&h,   g_h);
    cudaGetSymbolAddress((void**)&q,   g_q);
    cudaGetSymbolAddress((void**)&k,   g_k);
    cudaGetSymbolAddress((void**)&v,   g_v);
    cudaGetSymbolAddress((void**)&G,   g_G);
    cudaGetSymbolAddress((void**)&att, g_att);

    // h = relu(x @ W0 + b0)  [6400,256]@[256,512]
    {
        dim3 grid(HH / 64, NBS / 128);
        tgemm_kernel<true, true><<<grid, 256>>>(x, W0, b0, h, NBS, HH, DIN);
    }
    // q,k,v = h @ W{q,k,v}   [6400,512]@[512,512]
    {
        dim3 grid(HH / 64, NBS / 128);
        tgemm_kernel<false, false><<<grid, 256>>>(h, Wq, nullptr, q, NBS, HH, HH);
        tgemm_kernel<false, false><<<grid, 256>>>(h, Wk, nullptr, k, NBS, HH, HH);
        tgemm_kernel<false, false><<<grid, 256>>>(h, Wv, nullptr, v, NBS, HH, HH);
    }
    // per-batch Gram (scaled)
    gram_kernel<<<BB, 256>>>(q, k, G);
    // softmax + alpha + weighted V
    attn_kernel<<<NBS, 256>>>(G, v, alpha_out, att);
    // y = relu(att @ W1 + b1)  [6400,512]@[512,256]
    {
        dim3 grid(DOUT / 64, NBS / 128);
        tgemm_kernel<true, true><<<grid, 256>>>(att, W1, b1, y_out, NBS, DOUT, HH);
    }
}

// round 4
// speedup vs baseline: 1.6627x; 1.1505x over previous
#include <cuda_runtime.h>
#include <math.h>

#define BB 64
#define SS 100
#define DIN 256
#define HH 512
#define DOUT 256
#define WR 16
#define WIN 33
#define NBS (BB*SS)
#define STILE 4

// ---------------- scratch ----------------
__device__ float g_h  [NBS*HH];
__device__ float g_q  [NBS*HH];
__device__ float g_k  [NBS*HH];
__device__ float g_v  [NBS*HH];
__device__ float g_G  [BB*SS*SS];
__device__ float g_att[NBS*HH];

__device__ __forceinline__ unsigned f2tf(float x){
    unsigned r; asm("cvt.rna.tf32.f32 %0, %1;" : "=r"(r) : "f"(x)); return r;
}
__device__ __forceinline__ void mma_tf32(float c[4], unsigned a0,unsigned a1,unsigned a2,unsigned a3,
                                         unsigned b0, unsigned b1){
    asm volatile("mma.sync.aligned.m16n8k8.row.col.f32.tf32.tf32.f32 "
        "{%0,%1,%2,%3},{%4,%5,%6,%7},{%8,%9},{%0,%1,%2,%3};"
        : "+f"(c[0]),"+f"(c[1]),"+f"(c[2]),"+f"(c[3])
        : "r"(a0),"r"(a1),"r"(a2),"r"(a3),"r"(b0),"r"(b1));
}

// permuted position within a k-group of 8: logical kk -> 2*(kk&3) + (kk>>2)
// so thread t's operand pair (t, t+4) sits at positions (2t, 2t+1) -> one LDS.64.

// ---------------- tf32 GEMM: C = relu?(A@B + bias) ----------------
// A[M,K] rm, B[K,N] rm. BM=128 BN=64 BK=32, 256 thr, warp tile 32x32 (4x2 warps).
template<bool RELU, bool BIAS>
__global__ __launch_bounds__(256)
void tgemm_kernel(const float* __restrict__ A, const float* __restrict__ B,
                  const float* __restrict__ bias, float* __restrict__ C,
                  int M, int N, int K)
{
    const int BM=128, BN=64, BK=32, SA=36, SB=36;
    __shared__ unsigned As[BM*SA];
    __shared__ unsigned Bs[BN*SB];
    int tid = threadIdx.x, lane = tid & 31, w = tid >> 5;
    int wm = w & 3, wn = w >> 2;
    int g = lane >> 2, t = lane & 3;
    int bm = blockIdx.y * BM, bn = blockIdx.x * BN;

    float4 ar[4], br[2];
    float acc[2][4][4] = {};
    int NK = K / BK;

    #define LOADG(k0) {                                                        \
        _Pragma("unroll")                                                      \
        for (int i = 0; i < 4; i++) {                                          \
            int f = tid + i*256; int row = f>>3, c4 = (f&7)*4;                 \
            ar[i] = *(const float4*)&A[(size_t)(bm+row)*K + (k0) + c4];        \
        }                                                                      \
        _Pragma("unroll")                                                      \
        for (int i = 0; i < 2; i++) {                                          \
            int f = tid + i*256; int kk = f>>4, c4 = (f&15)*4;                 \
            br[i] = *(const float4*)&B[(size_t)((k0)+kk)*N + bn + c4];         \
        }                                                                      \
    }
    #define STORES() {                                                         \
        _Pragma("unroll")                                                      \
        for (int i = 0; i < 4; i++) {                                          \
            int f = tid + i*256; int row = f>>3, c4 = (f&7)*4;                 \
            int base = (c4>>3)*8 + (((c4&7)==4) ? 1 : 0);                      \
            unsigned* d = &As[row*SA + base];                                  \
            d[0]=f2tf(ar[i].x); d[2]=f2tf(ar[i].y);                            \
            d[4]=f2tf(ar[i].z); d[6]=f2tf(ar[i].w);                            \
        }                                                                      \
        _Pragma("unroll")                                                      \
        for (int i = 0; i < 2; i++) {                                          \
            int f = tid + i*256; int kk = f>>4, c4 = (f&15)*4;                 \
            int col = (kk>>3)*8 + 2*(kk&3) + ((kk&7)>>2);                      \
            Bs[(c4+0)*SB + col] = f2tf(br[i].x);                               \
            Bs[(c4+1)*SB + col] = f2tf(br[i].y);                               \
            Bs[(c4+2)*SB + col] = f2tf(br[i].z);                               \
            Bs[(c4+3)*SB + col] = f2tf(br[i].w);                               \
        }                                                                      \
    }

    LOADG(0); STORES(); __syncthreads();

    for (int kt = 0; kt < NK; kt++) {
        if (kt + 1 < NK) LOADG((kt+1)*BK);
        #pragma unroll
        for (int ks = 0; ks < 4; ks++) {
            unsigned a[2][4], b[4][2];
            #pragma unroll
            for (int mt = 0; mt < 2; mt++) {
                int r = wm*32 + mt*16 + g;
                uint2 lo = *(const uint2*)&As[r*SA + ks*8 + 2*t];
                uint2 hi = *(const uint2*)&As[(r+8)*SA + ks*8 + 2*t];
                a[mt][0]=lo.x; a[mt][1]=hi.x; a[mt][2]=lo.y; a[mt][3]=hi.y;
            }
            #pragma unroll
            for (int nt = 0; nt < 4; nt++) {
                int n = wn*32 + nt*8 + g;
                uint2 bb = *(const uint2*)&Bs[n*SB + ks*8 + 2*t];
                b[nt][0]=bb.x; b[nt][1]=bb.y;
            }
            #pragma unroll
            for (int mt = 0; mt < 2; mt++)
                #pragma unroll
                for (int nt = 0; nt < 4; nt++)
                    mma_tf32(acc[mt][nt], a[mt][0],a[mt][1],a[mt][2],a[mt][3],
                             b[nt][0], b[nt][1]);
        }
        __syncthreads();
        if (kt + 1 < NK) { STORES(); __syncthreads(); }
    }
    #undef LOADG
    #undef STORES

    #pragma unroll
    for (int mt = 0; mt < 2; mt++) {
        int r0 = bm + wm*32 + mt*16 + g;
        #pragma unroll
        for (int nt = 0; nt < 4; nt++) {
            int col = bn + wn*32 + nt*8 + 2*t;
            float bx = 0.f, by = 0.f;
            if (BIAS) { bx = bias[col]; by = bias[col+1]; }
            float2 o0, o1;
            o0.x = acc[mt][nt][0] + bx; o0.y = acc[mt][nt][1] + by;
            o1.x = acc[mt][nt][2] + bx; o1.y = acc[mt][nt][3] + by;
            if (RELU) {
                o0.x=fmaxf(o0.x,0.f); o0.y=fmaxf(o0.y,0.f);
                o1.x=fmaxf(o1.x,0.f); o1.y=fmaxf(o1.y,0.f);
            }
            *(float2*)&C[(size_t)r0*N + col]     = o0;
            *(float2*)&C[(size_t)(r0+8)*N + col] = o1;
        }
    }
}

// ---------------- per-batch Gram, N split in two: grid (2, 64) ----------------
// G[b,p,u] = q[b,p].k[b,u] / sqrt(H).  BM=128(p pad), BN=64(u), BK=32.
__global__ __launch_bounds__(256)
void gram_kernel(const float* __restrict__ q, const float* __restrict__ kmat,
                 float* __restrict__ G)
{
    const int SA=36, SB=36, BK=32;
    __shared__ unsigned As[128*SA];
    __shared__ unsigned Bs[64*SB];
    int b = blockIdx.y;
    int n0 = blockIdx.x * 64;
    int tid = threadIdx.x, lane = tid & 31, w = tid >> 5;
    int wm = w & 3, wn = w >> 2;
    int g = lane >> 2, t = lane & 3;
    const float* qbp = q    + (size_t)b*SS*HH;
    const float* kbp = kmat + (size_t)b*SS*HH;

    float4 ar[4], br[2];
    float acc[2][4][4] = {};
    const int NK = HH / BK;

    #define LOADG(k0) {                                                        \
        _Pragma("unroll")                                                      \
        for (int i = 0; i < 4; i++) {                                          \
            int f = tid + i*256; int row = f>>3, c4 = (f&7)*4;                 \
            int sr = row < SS ? row : SS-1;                                    \
            ar[i] = *(const float4*)&qbp[(size_t)sr*HH + (k0) + c4];           \
        }                                                                      \
        _Pragma("unroll")                                                      \
        for (int i = 0; i < 2; i++) {                                          \
            int f = tid + i*256; int u = f>>3, c4 = (f&7)*4;                   \
            int su = (n0+u) < SS ? (n0+u) : SS-1;                              \
            br[i] = *(const float4*)&kbp[(size_t)su*HH + (k0) + c4];           \
        }                                                                      \
    }
    #define STORES() {                                                         \
        _Pragma("unroll")                                                      \
        for (int i = 0; i < 4; i++) {                                          \
            int f = tid + i*256; int row = f>>3, c4 = (f&7)*4;                 \
            int base = (c4>>3)*8 + (((c4&7)==4) ? 1 : 0);                      \
            unsigned* d = &As[row*SA + base];                                  \
            d[0]=f2tf(ar[i].x); d[2]=f2tf(ar[i].y);                            \
            d[4]=f2tf(ar[i].z); d[6]=f2tf(ar[i].w);                            \
        }                                                                      \
        _Pragma("unroll")                                                      \
        for (int i = 0; i < 2; i++) {                                          \
            int f = tid + i*256; int u = f>>3, c4 = (f&7)*4;                   \
            int base = (c4>>3)*8 + (((c4&7)==4) ? 1 : 0);                      \
            unsigned* d = &Bs[u*SB + base];                                    \
            d[0]=f2tf(br[i].x); d[2]=f2tf(br[i].y);                            \
            d[4]=f2tf(br[i].z); d[6]=f2tf(br[i].w);                            \
        }                                                                      \
    }

    LOADG(0); STORES(); __syncthreads();

    for (int kt = 0; kt < NK; kt++) {
        if (kt + 1 < NK) LOADG((kt+1)*BK);
        #pragma unroll
        for (int ks = 0; ks < 4; ks++) {
            unsigned a[2][4], bfr[4][2];
            #pragma unroll
            for (int mt = 0; mt < 2; mt++) {
                int r = wm*32 + mt*16 + g;
                uint2 lo = *(const uint2*)&As[r*SA + ks*8 + 2*t];
                uint2 hi = *(const uint2*)&As[(r+8)*SA + ks*8 + 2*t];
                a[mt][0]=lo.x; a[mt][1]=hi.x; a[mt][2]=lo.y; a[mt][3]=hi.y;
            }
            #pragma unroll
            for (int nt = 0; nt < 4; nt++) {
                int n = wn*32 + nt*8 + g;
                uint2 bb = *(const uint2*)&Bs[n*SB + ks*8 + 2*t];
                bfr[nt][0]=bb.x; bfr[nt][1]=bb.y;
            }
            #pragma unroll
            for (int mt = 0; mt < 2; mt++)
                #pragma unroll
                for (int nt = 0; nt < 4; nt++)
                    mma_tf32(acc[mt][nt], a[mt][0],a[mt][1],a[mt][2],a[mt][3],
                             bfr[nt][0], bfr[nt][1]);
        }
        __syncthreads();
        if (kt + 1 < NK) { STORES(); __syncthreads(); }
    }
    #undef LOADG
    #undef STORES

    const float invs = 0.044194173824159216f;  // 1/sqrt(512)
    float* Gb = G + (size_t)b*SS*SS;
    #pragma unroll
    for (int mt = 0; mt < 2; mt++) {
        int r0 = wm*32 + mt*16 + g;
        #pragma unroll
        for (int nt = 0; nt < 4; nt++) {
            int col = n0 + wn*32 + nt*8 + 2*t;
            if (col + 1 < SS) {
                if (r0 < SS) {
                    Gb[r0*SS + col]     = acc[mt][nt][0]*invs;
                    Gb[r0*SS + col + 1] = acc[mt][nt][1]*invs;
                }
                if (r0 + 8 < SS) {
                    Gb[(r0+8)*SS + col]     = acc[mt][nt][2]*invs;
                    Gb[(r0+8)*SS + col + 1] = acc[mt][nt][3]*invs;
                }
            } else if (col < SS) {  // col == 99
                if (r0 < SS)     Gb[r0*SS + col]     = acc[mt][nt][0]*invs;
                if (r0 + 8 < SS) Gb[(r0+8)*SS + col] = acc[mt][nt][2]*invs;
            }
        }
    }
}

// ---------------- softmax + beta + weighted V, STILE positions per block ----------------
__global__ __launch_bounds__(256)
void attn_kernel(const float* __restrict__ G, const float* __restrict__ v,
                 float* __restrict__ alpha_out, float* __restrict__ att)
{
    int blk = blockIdx.x;
    int b  = blk / (SS / STILE);
    int s0 = (blk % (SS / STILE)) * STILE;
    __shared__ float dmat[STILE][WIN * WIN];
    __shared__ float beta[STILE][WIN];
    const float* Gb = G + (size_t)b*SS*SS;
    int tid = threadIdx.x;

    for (int idx = tid; idx < STILE*WIN*WIN; idx += 256) {
        int si = idx / (WIN*WIN), r = idx % (WIN*WIN);
        int w_ = r / WIN, u = r % WIN;
        int s = s0 + si;
        int p  = s + WR - w_;
        int pu = s + WR - u;
        float val = 0.f;
        if (p >= 0 && p < SS && pu >= 0 && pu < SS)
            val = Gb[p*SS + pu];
        dmat[si][r] = val;
    }
    __syncthreads();

    int warp = tid >> 5, lane = tid & 31;
    for (int rr = warp; rr < STILE*WIN; rr += 8) {
        int si = rr / WIN, r = rr % WIN;
        float* row = &dmat[si][r*WIN];
        float x0 = row[lane];
        float x1 = (lane == 0) ? row[32] : -1e30f;
        float m = fmaxf(x0, x1);
#pragma unroll
        for (int o = 16; o; o >>= 1)
            m = fmaxf(m, __shfl_xor_sync(0xffffffffu, m, o));
        float e0 = __expf(x0 - m);
        float e1 = (lane == 0) ? __expf(x1 - m) : 0.f;
        float ssum = e0 + e1;
#pragma unroll
        for (int o = 16; o; o >>= 1)
            ssum += __shfl_xor_sync(0xffffffffu, ssum, o);
        float rinv = __frcp_rn(ssum);
        e0 *= rinv; e1 *= rinv;
        row[lane] = e0;
        if (lane == 0) row[32] = e1;
        float* ao = alpha_out + (size_t)(b*SS + s0 + si)*(WIN*WIN) + r*WIN;
        ao[lane] = e0;
        if (lane == 0) ao[32] = e1;
    }
    __syncthreads();

    for (int idx = tid; idx < STILE*WIN; idx += 256) {
        int si = idx / WIN, u = idx % WIN;
        float acc = 0.f;
        for (int r = 0; r < WIN; r++) acc += dmat[si][r*WIN + u];
        beta[si][u] = acc;
    }
    __syncthreads();

    int h2 = tid * 2;
    float2 acc[STILE];
#pragma unroll
    for (int si = 0; si < STILE; si++) { acc[si].x = 0.f; acc[si].y = 0.f; }

#pragma unroll
    for (int j = 0; j < STILE - 1 + 2*WR + 1; j++) {   // 36 window positions
        int p = s0 - WR + j;
        if (p >= 0 && p < SS) {
            float2 vr = *(const float2*)&v[(size_t)(b*SS + p)*HH + h2];
#pragma unroll
            for (int si = 0; si < STILE; si++) {
                int u = si + 2*WR - j;
                if (u >= 0 && u < WIN) {
                    float bu = beta[si][u];
                    acc[si].x = fmaf(bu, vr.x, acc[si].x);
                    acc[si].y = fmaf(bu, vr.y, acc[si].y);
                }
            }
        }
    }
#pragma unroll
    for (int si = 0; si < STILE; si++)
        *(float2*)&att[(size_t)(b*SS + s0 + si)*HH + h2] = acc[si];
}

// ---------------- launch ----------------
extern "C" void kernel_launch(void* const* d_in, const int* in_sizes, int n_in,
                              void* d_out, int out_size)
{
    const float* x  = (const float*)d_in[0];
    const float* W0 = (const float*)d_in[1];
    const float* b0 = (const float*)d_in[2];
    const float* Wq = (const float*)d_in[3];
    const float* Wk = (const float*)d_in[4];
    const float* Wv = (const float*)d_in[5];
    const float* W1 = (const float*)d_in[6];
    const float* b1 = (const float*)d_in[7];
    float* out = (float*)d_out;
    float* y_out     = out;
    float* alpha_out = out + (size_t)NBS * DOUT;

    float *h, *q, *k, *v, *G, *att;
    cudaGetSymbolAddress((void**)&h,   g_h);
    cudaGetSymbolAddress((void**)&q,   g_q);
    cudaGetSymbolAddress((void**)&k,   g_k);
    cudaGetSymbolAddress((void**)&v,   g_v);
    cudaGetSymbolAddress((void**)&G,   g_G);
    cudaGetSymbolAddress((void**)&att, g_att);

    {
        dim3 grid(HH / 64, NBS / 128);
        tgemm_kernel<true, true><<<grid, 256>>>(x, W0, b0, h, NBS, HH, DIN);
        tgemm_kernel<false, false><<<grid, 256>>>(h, Wq, nullptr, q, NBS, HH, HH);
        tgemm_kernel<false, false><<<grid, 256>>>(h, Wk, nullptr, k, NBS, HH, HH);
        tgemm_kernel<false, false><<<grid, 256>>>(h, Wv, nullptr, v, NBS, HH, HH);
    }
    {
        dim3 grid(2, BB);
        gram_kernel<<<grid, 256>>>(q, k, G);
    }
    attn_kernel<<<NBS / STILE, 256>>>(G, v, alpha_out, att);
    {
        dim3 grid(DOUT / 64, NBS / 128);
        tgemm_kernel<true, true><<<grid, 256>>>(att, W1, b1, y_out, NBS, DOUT, HH);
    }
}

// round 6
// speedup vs baseline: 2.4944x; 1.5002x over previous
#include <cuda_runtime.h>
#include <stdint.h>
#include <math.h>

#define BB 64
#define SS 100
#define DIN 256
#define HH 512
#define DOUT 256
#define WR 16
#define WIN 33
#define NBS (BB*SS)
#define STILE 4

// ---------------- scratch ----------------
__device__ float g_x  [NBS*DIN];
__device__ float g_w0 [DIN*HH];
__device__ float g_wq [HH*HH];
__device__ float g_wk [HH*HH];
__device__ float g_wv [HH*HH];
__device__ float g_w1 [HH*DOUT];
__device__ float g_h  [NBS*HH];
__device__ float g_q  [NBS*HH];
__device__ float g_k  [NBS*HH];
__device__ float g_v  [NBS*HH];
__device__ float g_G  [BB*SS*SS];
__device__ float g_att[NBS*HH];

__device__ __forceinline__ unsigned f2tf(float x){
    unsigned r; asm("cvt.rna.tf32.f32 %0, %1;" : "=r"(r) : "f"(x)); return r;
}
__device__ __forceinline__ float roundtf(float x){
    return __uint_as_float(f2tf(x));
}
__device__ __forceinline__ void mma_tf32(float c[4], unsigned a0,unsigned a1,unsigned a2,unsigned a3,
                                         unsigned b0, unsigned b1){
    asm volatile("mma.sync.aligned.m16n8k8.row.col.f32.tf32.tf32.f32 "
        "{%0,%1,%2,%3},{%4,%5,%6,%7},{%8,%9},{%0,%1,%2,%3};"
        : "+f"(c[0]),"+f"(c[1]),"+f"(c[2]),"+f"(c[3])
        : "r"(a0),"r"(a1),"r"(a2),"r"(a3),"r"(b0),"r"(b1));
}
__device__ __forceinline__ uint32_t smem_u32(const void* p){
    uint32_t a;
    asm("{ .reg .u64 t; cvta.to.shared.u64 t, %1; cvt.u32.u64 %0, t; }" : "=r"(a) : "l"(p));
    return a;
}
__device__ __forceinline__ void cp16(void* dst, const void* src){
    uint32_t d = smem_u32(dst);
    asm volatile("cp.async.ca.shared.global [%0], [%1], 16;" :: "r"(d), "l"(src));
}
#define CP_COMMIT() asm volatile("cp.async.commit_group;" ::: "memory")
#define CP_WAIT(n)  asm volatile("cp.async.wait_group %0;" :: "n"(n) : "memory")

// ---------------- tf32 prepass rounding ----------------
__global__ __launch_bounds__(256)
void roundtf_kernel(const float* __restrict__ src, float* __restrict__ dst, int n4)
{
    int i = blockIdx.x * 256 + threadIdx.x;
    if (i >= n4) return;
    float4 v = ((const float4*)src)[i];
    v.x = roundtf(v.x); v.y = roundtf(v.y);
    v.z = roundtf(v.z); v.w = roundtf(v.w);
    ((float4*)dst)[i] = v;
}

// ---------------- tf32 GEMM, cp.async double-buffered ----------------
// A[M,K] rm (already tf32-rounded), B[K,N] rm (tf32-rounded), C = relu?(A@B + bias).
// BM=128 BN=64 BK=32, 256 thr, warp tile 32x32 (4x2 warp grid).
// smem (floats): As[2][128*36] then Bs[2][32*72] -> 55296 bytes dynamic.
#define AS_STG (128*36)
#define BS_STG (32*72)
#define SMEM_GEMM ((2*AS_STG + 2*BS_STG) * 4)

template<bool RELU, bool BIAS, bool ROUND>
__global__ __launch_bounds__(256)
void tgemm_kernel(const float* __restrict__ A, const float* __restrict__ B,
                  const float* __restrict__ bias, float* __restrict__ C,
                  int M, int N, int K)
{
    extern __shared__ float smem[];
    const int SA = 36, SB = 72, BK = 32;
    int tid = threadIdx.x, lane = tid & 31, w = tid >> 5;
    int wm = w & 3, wn = w >> 2;
    int g = lane >> 2, t = lane & 3;
    int bm = blockIdx.y * 128, bn = blockIdx.x * 64;
    int NK = K / BK;

    float acc[2][4][4] = {};

    #define ISSUE(kt) {                                                        \
        float* Asd = smem + ((kt)&1)*AS_STG;                                   \
        float* Bsd = smem + 2*AS_STG + ((kt)&1)*BS_STG;                        \
        int k0 = (kt)*BK;                                                      \
        _Pragma("unroll")                                                      \
        for (int i = 0; i < 4; i++) {                                          \
            int f = tid + i*256; int row = f>>3, c4 = f&7;                     \
            cp16(&Asd[row*SA + c4*4], &A[(size_t)(bm+row)*K + k0 + c4*4]);     \
        }                                                                      \
        _Pragma("unroll")                                                      \
        for (int i = 0; i < 2; i++) {                                          \
            int f = tid + i*256; int kk = f>>4, n4 = f&15;                     \
            cp16(&Bsd[kk*SB + n4*4], &B[(size_t)(k0+kk)*N + bn + n4*4]);       \
        }                                                                      \
        CP_COMMIT();                                                           \
    }

    ISSUE(0);
    for (int kt = 0; kt < NK; kt++) {
        if (kt + 1 < NK) { ISSUE(kt+1); CP_WAIT(1); }
        else             { CP_WAIT(0); }
        __syncthreads();
        const unsigned* As = (const unsigned*)(smem + (kt&1)*AS_STG);
        const unsigned* Bs = (const unsigned*)(smem + 2*AS_STG + (kt&1)*BS_STG);
        #pragma unroll
        for (int ks = 0; ks < 4; ks++) {
            unsigned a[2][4], b[4][2];
            #pragma unroll
            for (int mt = 0; mt < 2; mt++) {
                int m0 = wm*32 + mt*16;
                const unsigned* ap = &As[(m0+g)*SA + ks*8 + t];
                a[mt][0]=ap[0]; a[mt][1]=ap[8*SA]; a[mt][2]=ap[4]; a[mt][3]=ap[8*SA+4];
            }
            #pragma unroll
            for (int nt = 0; nt < 4; nt++) {
                int n0 = wn*32 + nt*8;
                const unsigned* bp = &Bs[(ks*8+t)*SB + n0 + g];
                b[nt][0]=bp[0]; b[nt][1]=bp[4*SB];
            }
            #pragma unroll
            for (int mt = 0; mt < 2; mt++)
                #pragma unroll
                for (int nt = 0; nt < 4; nt++)
                    mma_tf32(acc[mt][nt], a[mt][0],a[mt][1],a[mt][2],a[mt][3],
                             b[nt][0], b[nt][1]);
        }
        __syncthreads();
    }
    #undef ISSUE

    #pragma unroll
    for (int mt = 0; mt < 2; mt++) {
        int r0 = bm + wm*32 + mt*16 + g;
        #pragma unroll
        for (int nt = 0; nt < 4; nt++) {
            int col = bn + wn*32 + nt*8 + 2*t;
            float bx = 0.f, by = 0.f;
            if (BIAS) { bx = bias[col]; by = bias[col+1]; }
            float2 o0, o1;
            o0.x = acc[mt][nt][0] + bx; o0.y = acc[mt][nt][1] + by;
            o1.x = acc[mt][nt][2] + bx; o1.y = acc[mt][nt][3] + by;
            if (RELU) {
                o0.x=fmaxf(o0.x,0.f); o0.y=fmaxf(o0.y,0.f);
                o1.x=fmaxf(o1.x,0.f); o1.y=fmaxf(o1.y,0.f);
            }
            if (ROUND) {
                o0.x=roundtf(o0.x); o0.y=roundtf(o0.y);
                o1.x=roundtf(o1.x); o1.y=roundtf(o1.y);
            }
            *(float2*)&C[(size_t)r0*N + col]     = o0;
            *(float2*)&C[(size_t)(r0+8)*N + col] = o1;
        }
    }
}

// ---------------- per-batch Gram, grid (2, 64) ----------------
__global__ __launch_bounds__(256)
void gram_kernel(const float* __restrict__ q, const float* __restrict__ kmat,
                 float* __restrict__ G)
{
    const int SA=36, SB=36, BK=32;
    __shared__ unsigned As[128*SA];
    __shared__ unsigned Bs[64*SB];
    int b = blockIdx.y;
    int n0 = blockIdx.x * 64;
    int tid = threadIdx.x, lane = tid & 31, w = tid >> 5;
    int wm = w & 3, wn = w >> 2;
    int g = lane >> 2, t = lane & 3;
    const float* qbp = q    + (size_t)b*SS*HH;
    const float* kbp = kmat + (size_t)b*SS*HH;

    float4 ar[4], br[2];
    float acc[2][4][4] = {};
    const int NK = HH / BK;

    #define LOADG(k0) {                                                        \
        _Pragma("unroll")                                                      \
        for (int i = 0; i < 4; i++) {                                          \
            int f = tid + i*256; int row = f>>3, c4 = (f&7)*4;                 \
            int sr = row < SS ? row : SS-1;                                    \
            ar[i] = *(const float4*)&qbp[(size_t)sr*HH + (k0) + c4];           \
        }                                                                      \
        _Pragma("unroll")                                                      \
        for (int i = 0; i < 2; i++) {                                          \
            int f = tid + i*256; int u = f>>3, c4 = (f&7)*4;                   \
            int su = (n0+u) < SS ? (n0+u) : SS-1;                              \
            br[i] = *(const float4*)&kbp[(size_t)su*HH + (k0) + c4];           \
        }                                                                      \
    }
    #define STORES() {                                                         \
        _Pragma("unroll")                                                      \
        for (int i = 0; i < 4; i++) {                                          \
            int f = tid + i*256; int row = f>>3, c4 = (f&7)*4;                 \
            int base = (c4>>3)*8 + (((c4&7)==4) ? 1 : 0);                      \
            unsigned* d = &As[row*SA + base];                                  \
            d[0]=f2tf(ar[i].x); d[2]=f2tf(ar[i].y);                            \
            d[4]=f2tf(ar[i].z); d[6]=f2tf(ar[i].w);                            \
        }                                                                      \
        _Pragma("unroll")                                                      \
        for (int i = 0; i < 2; i++) {                                          \
            int f = tid + i*256; int u = f>>3, c4 = (f&7)*4;                   \
            int base = (c4>>3)*8 + (((c4&7)==4) ? 1 : 0);                      \
            unsigned* d = &Bs[u*SB + base];                                    \
            d[0]=f2tf(br[i].x); d[2]=f2tf(br[i].y);                            \
            d[4]=f2tf(br[i].z); d[6]=f2tf(br[i].w);                            \
        }                                                                      \
    }

    LOADG(0); STORES(); __syncthreads();

    for (int kt = 0; kt < NK; kt++) {
        if (kt + 1 < NK) LOADG((kt+1)*BK);
        #pragma unroll
        for (int ks = 0; ks < 4; ks++) {
            unsigned a[2][4], bfr[4][2];
            #pragma unroll
            for (int mt = 0; mt < 2; mt++) {
                int r = wm*32 + mt*16 + g;
                uint2 lo = *(const uint2*)&As[r*SA + ks*8 + 2*t];
                uint2 hi = *(const uint2*)&As[(r+8)*SA + ks*8 + 2*t];
                a[mt][0]=lo.x; a[mt][1]=hi.x; a[mt][2]=lo.y; a[mt][3]=hi.y;
            }
            #pragma unroll
            for (int nt = 0; nt < 4; nt++) {
                int n = wn*32 + nt*8 + g;
                uint2 bb = *(const uint2*)&Bs[n*SB + ks*8 + 2*t];
                bfr[nt][0]=bb.x; bfr[nt][1]=bb.y;
            }
            #pragma unroll
            for (int mt = 0; mt < 2; mt++)
                #pragma unroll
                for (int nt = 0; nt < 4; nt++)
                    mma_tf32(acc[mt][nt], a[mt][0],a[mt][1],a[mt][2],a[mt][3],
                             bfr[nt][0], bfr[nt][1]);
        }
        __syncthreads();
        if (kt + 1 < NK) { STORES(); __syncthreads(); }
    }
    #undef LOADG
    #undef STORES

    const float invs = 0.044194173824159216f;  // 1/sqrt(512)
    float* Gb = G + (size_t)b*SS*SS;
    #pragma unroll
    for (int mt = 0; mt < 2; mt++) {
        int r0 = wm*32 + mt*16 + g;
        #pragma unroll
        for (int nt = 0; nt < 4; nt++) {
            int col = n0 + wn*32 + nt*8 + 2*t;
            if (col + 1 < SS) {
                if (r0 < SS) {
                    Gb[r0*SS + col]     = acc[mt][nt][0]*invs;
                    Gb[r0*SS + col + 1] = acc[mt][nt][1]*invs;
                }
                if (r0 + 8 < SS) {
                    Gb[(r0+8)*SS + col]     = acc[mt][nt][2]*invs;
                    Gb[(r0+8)*SS + col + 1] = acc[mt][nt][3]*invs;
                }
            } else if (col < SS) {
                if (r0 < SS)     Gb[r0*SS + col]     = acc[mt][nt][0]*invs;
                if (r0 + 8 < SS) Gb[(r0+8)*SS + col] = acc[mt][nt][2]*invs;
            }
        }
    }
}

// ---------------- softmax + beta + weighted V ----------------
__global__ __launch_bounds__(256)
void attn_kernel(const float* __restrict__ G, const float* __restrict__ v,
                 float* __restrict__ alpha_out, float* __restrict__ att)
{
    int blk = blockIdx.x;
    int b  = blk / (SS / STILE);
    int s0 = (blk % (SS / STILE)) * STILE;
    __shared__ float dmat[STILE][WIN * WIN];
    __shared__ float beta[STILE][WIN];
    const float* Gb = G + (size_t)b*SS*SS;
    int tid = threadIdx.x;

    for (int idx = tid; idx < STILE*WIN*WIN; idx += 256) {
        int si = idx / (WIN*WIN), r = idx % (WIN*WIN);
        int w_ = r / WIN, u = r % WIN;
        int s = s0 + si;
        int p  = s + WR - w_;
        int pu = s + WR - u;
        float val = 0.f;
        if (p >= 0 && p < SS && pu >= 0 && pu < SS)
            val = Gb[p*SS + pu];
        dmat[si][r] = val;
    }
    __syncthreads();

    int warp = tid >> 5, lane = tid & 31;
    for (int rr = warp; rr < STILE*WIN; rr += 8) {
        int si = rr / WIN, r = rr % WIN;
        float* row = &dmat[si][r*WIN];
        float x0 = row[lane];
        float x1 = (lane == 0) ? row[32] : -1e30f;
        float m = fmaxf(x0, x1);
#pragma unroll
        for (int o = 16; o; o >>= 1)
            m = fmaxf(m, __shfl_xor_sync(0xffffffffu, m, o));
        float e0 = __expf(x0 - m);
        float e1 = (lane == 0) ? __expf(x1 - m) : 0.f;
        float ssum = e0 + e1;
#pragma unroll
        for (int o = 16; o; o >>= 1)
            ssum += __shfl_xor_sync(0xffffffffu, ssum, o);
        float rinv = __frcp_rn(ssum);
        e0 *= rinv; e1 *= rinv;
        row[lane] = e0;
        if (lane == 0) row[32] = e1;
        float* ao = alpha_out + (size_t)(b*SS + s0 + si)*(WIN*WIN) + r*WIN;
        ao[lane] = e0;
        if (lane == 0) ao[32] = e1;
    }
    __syncthreads();

    for (int idx = tid; idx < STILE*WIN; idx += 256) {
        int si = idx / WIN, u = idx % WIN;
        float acc = 0.f;
        for (int r = 0; r < WIN; r++) acc += dmat[si][r*WIN + u];
        beta[si][u] = acc;
    }
    __syncthreads();

    int h2 = tid * 2;
    float2 acc[STILE];
#pragma unroll
    for (int si = 0; si < STILE; si++) { acc[si].x = 0.f; acc[si].y = 0.f; }

#pragma unroll
    for (int j = 0; j < STILE - 1 + 2*WR + 1; j++) {
        int p = s0 - WR + j;
        if (p >= 0 && p < SS) {
            float2 vr = *(const float2*)&v[(size_t)(b*SS + p)*HH + h2];
#pragma unroll
            for (int si = 0; si < STILE; si++) {
                int u = si + 2*WR - j;
                if (u >= 0 && u < WIN) {
                    float bu = beta[si][u];
                    acc[si].x = fmaf(bu, vr.x, acc[si].x);
                    acc[si].y = fmaf(bu, vr.y, acc[si].y);
                }
            }
        }
    }
#pragma unroll
    for (int si = 0; si < STILE; si++) {
        float2 o;
        o.x = roundtf(acc[si].x);   // att feeds the final tf32 GEMM
        o.y = roundtf(acc[si].y);
        *(float2*)&att[(size_t)(b*SS + s0 + si)*HH + h2] = o;
    }
}

// ---------------- launch ----------------
extern "C" void kernel_launch(void* const* d_in, const int* in_sizes, int n_in,
                              void* d_out, int out_size)
{
    const float* x  = (const float*)d_in[0];
    const float* W0 = (const float*)d_in[1];
    const float* b0 = (const float*)d_in[2];
    const float* Wq = (const float*)d_in[3];
    const float* Wk = (const float*)d_in[4];
    const float* Wv = (const float*)d_in[5];
    const float* W1 = (const float*)d_in[6];
    const float* b1 = (const float*)d_in[7];
    float* out = (float*)d_out;
    float* y_out     = out;
    float* alpha_out = out + (size_t)NBS * DOUT;

    float *xr,*w0r,*wqr,*wkr,*wvr,*w1r,*h,*q,*k,*v,*G,*att;
    cudaGetSymbolAddress((void**)&xr,  g_x);
    cudaGetSymbolAddress((void**)&w0r, g_w0);
    cudaGetSymbolAddress((void**)&wqr, g_wq);
    cudaGetSymbolAddress((void**)&wkr, g_wk);
    cudaGetSymbolAddress((void**)&wvr, g_wv);
    cudaGetSymbolAddress((void**)&w1r, g_w1);
    cudaGetSymbolAddress((void**)&h,   g_h);
    cudaGetSymbolAddress((void**)&q,   g_q);
    cudaGetSymbolAddress((void**)&k,   g_k);
    cudaGetSymbolAddress((void**)&v,   g_v);
    cudaGetSymbolAddress((void**)&G,   g_G);
    cudaGetSymbolAddress((void**)&att, g_att);

    cudaFuncSetAttribute(tgemm_kernel<true,  true,  true >, cudaFuncAttributeMaxDynamicSharedMemorySize, SMEM_GEMM);
    cudaFuncSetAttribute(tgemm_kernel<false, false, true >, cudaFuncAttributeMaxDynamicSharedMemorySize, SMEM_GEMM);
    cudaFuncSetAttribute(tgemm_kernel<false, false, false>, cudaFuncAttributeMaxDynamicSharedMemorySize, SMEM_GEMM);
    cudaFuncSetAttribute(tgemm_kernel<true,  true,  false>, cudaFuncAttributeMaxDynamicSharedMemorySize, SMEM_GEMM);

    // tf32 rounding prepasses
    roundtf_kernel<<<(NBS*DIN/4 + 255)/256, 256>>>(x,  xr,  NBS*DIN/4);
    roundtf_kernel<<<(DIN*HH/4  + 255)/256, 256>>>(W0, w0r, DIN*HH/4);
    roundtf_kernel<<<(HH*HH/4   + 255)/256, 256>>>(Wq, wqr, HH*HH/4);
    roundtf_kernel<<<(HH*HH/4   + 255)/256, 256>>>(Wk, wkr, HH*HH/4);
    roundtf_kernel<<<(HH*HH/4   + 255)/256, 256>>>(Wv, wvr, HH*HH/4);
    roundtf_kernel<<<(HH*DOUT/4 + 255)/256, 256>>>(W1, w1r, HH*DOUT/4);

    // h = relu(x@W0 + b0), output tf32-rounded (feeds QKV GEMMs)
    tgemm_kernel<true, true, true><<<dim3(HH/64, NBS/128), 256, SMEM_GEMM>>>(
        xr, w0r, b0, h, NBS, HH, DIN);
    // q,k (tf32-rounded is harmless — gram re-rounds), v plain fp32
    tgemm_kernel<false, false, false><<<dim3(HH/64, NBS/128), 256, SMEM_GEMM>>>(
        h, wqr, nullptr, q, NBS, HH, HH);
    tgemm_kernel<false, false, false><<<dim3(HH/64, NBS/128), 256, SMEM_GEMM>>>(
        h, wkr, nullptr, k, NBS, HH, HH);
    tgemm_kernel<false, false, false><<<dim3(HH/64, NBS/128), 256, SMEM_GEMM>>>(
        h, wvr, nullptr, v, NBS, HH, HH);
    // Gram + attention
    gram_kernel<<<dim3(2, BB), 256>>>(q, k, G);
    attn_kernel<<<NBS/STILE, 256>>>(G, v, alpha_out, att);
    // y = relu(att@W1 + b1)
    tgemm_kernel<true, true, false><<<dim3(DOUT/64, NBS/128), 256, SMEM_GEMM>>>(
        att, w1r, b1, y_out, NBS, DOUT, HH);
}

// round 7
// speedup vs baseline: 2.7067x; 1.0851x over previous
#include <cuda_runtime.h>
#include <stdint.h>
#include <math.h>

#define BB 64
#define SS 100
#define DIN 256
#define HH 512
#define DOUT 256
#define WR 16
#define WIN 33
#define NBS (BB*SS)
#define STILE 4

// ---------------- scratch ----------------
__device__ float g_x  [NBS*DIN];
__device__ float g_w0 [DIN*HH];
__device__ float g_wq [HH*HH];
__device__ float g_wk [HH*HH];
__device__ float g_wv [HH*HH];
__device__ float g_w1 [HH*DOUT];
__device__ float g_h  [NBS*HH];
__device__ float g_q  [NBS*HH];
__device__ float g_k  [NBS*HH];
__device__ float g_v  [NBS*HH];
__device__ float g_G  [BB*SS*SS];
__device__ float g_att[NBS*HH];

__device__ __forceinline__ unsigned f2tf(float x){
    unsigned r; asm("cvt.rna.tf32.f32 %0, %1;" : "=r"(r) : "f"(x)); return r;
}
__device__ __forceinline__ float roundtf(float x){
    return __uint_as_float(f2tf(x));
}
__device__ __forceinline__ void mma_tf32(float c[4], unsigned a0,unsigned a1,unsigned a2,unsigned a3,
                                         unsigned b0, unsigned b1){
    asm volatile("mma.sync.aligned.m16n8k8.row.col.f32.tf32.tf32.f32 "
        "{%0,%1,%2,%3},{%4,%5,%6,%7},{%8,%9},{%0,%1,%2,%3};"
        : "+f"(c[0]),"+f"(c[1]),"+f"(c[2]),"+f"(c[3])
        : "r"(a0),"r"(a1),"r"(a2),"r"(a3),"r"(b0),"r"(b1));
}
__device__ __forceinline__ uint32_t smem_u32(const void* p){
    uint32_t a;
    asm("{ .reg .u64 t; cvta.to.shared.u64 t, %1; cvt.u32.u64 %0, t; }" : "=r"(a) : "l"(p));
    return a;
}
__device__ __forceinline__ void cp16(void* dst, const void* src){
    uint32_t d = smem_u32(dst);
    asm volatile("cp.async.ca.shared.global [%0], [%1], 16;" :: "r"(d), "l"(src));
}
#define CP_COMMIT() asm volatile("cp.async.commit_group;" ::: "memory")
#define CP_WAIT(n)  asm volatile("cp.async.wait_group %0;" :: "n"(n) : "memory")

// ---------------- tf32 rounding prepasses (fused) ----------------
__global__ __launch_bounds__(256)
void roundtf_kernel(const float* __restrict__ src, float* __restrict__ dst, int n4)
{
    int i = blockIdx.x * 256 + threadIdx.x;
    if (i >= n4) return;
    float4 v = ((const float4*)src)[i];
    v.x = roundtf(v.x); v.y = roundtf(v.y);
    v.z = roundtf(v.z); v.w = roundtf(v.w);
    ((float4*)dst)[i] = v;
}

// All five weight tensors in one launch. Sizes in float4:
// W0: 32768 | Wq: 65536 | Wk: 65536 | Wv: 65536 | W1: 32768  -> 262144 total
__global__ __launch_bounds__(256)
void round_weights_kernel(const float* __restrict__ W0, const float* __restrict__ Wq,
                          const float* __restrict__ Wk, const float* __restrict__ Wv,
                          const float* __restrict__ W1,
                          float* __restrict__ dW0, float* __restrict__ dWq,
                          float* __restrict__ dWk, float* __restrict__ dWv,
                          float* __restrict__ dW1)
{
    int i = blockIdx.x * 256 + threadIdx.x;   // [0, 262144)
    const float4* s; float4* d; int o;
    if      (i < 32768)  { s = (const float4*)W0; d = (float4*)dW0; o = 0; }
    else if (i < 98304)  { s = (const float4*)Wq; d = (float4*)dWq; o = 32768; }
    else if (i < 163840) { s = (const float4*)Wk; d = (float4*)dWk; o = 98304; }
    else if (i < 229376) { s = (const float4*)Wv; d = (float4*)dWv; o = 163840; }
    else                 { s = (const float4*)W1; d = (float4*)dW1; o = 229376; }
    int j = i - o;
    float4 v = s[j];
    v.x = roundtf(v.x); v.y = roundtf(v.y);
    v.z = roundtf(v.z); v.w = roundtf(v.w);
    d[j] = v;
}

// ---------------- tf32 GEMM core, cp.async double-buffered ----------------
// A[M,K] rm (tf32-rounded), B[K,N] rm (tf32-rounded), C = relu?(A@B + bias).
// BM=128 BN=64 BK=32, 256 thr, warp tile 32x32 (4x2 warp grid).
#define AS_STG (128*36)
#define BS_STG (32*72)
#define SMEM_GEMM ((2*AS_STG + 2*BS_STG) * 4)

template<bool RELU, bool BIAS, bool ROUND>
__device__ __forceinline__
void gemm_core(const float* __restrict__ A, const float* __restrict__ B,
               const float* __restrict__ bias, float* __restrict__ C,
               int N, int K, int bm, int bn, float* smem)
{
    const int SA = 36, SB = 72, BK = 32;
    int tid = threadIdx.x, lane = tid & 31, w = tid >> 5;
    int wm = w & 3, wn = w >> 2;
    int g = lane >> 2, t = lane & 3;
    int NK = K / BK;

    float acc[2][4][4] = {};

    #define ISSUE(kt) {                                                        \
        float* Asd = smem + ((kt)&1)*AS_STG;                                   \
        float* Bsd = smem + 2*AS_STG + ((kt)&1)*BS_STG;                        \
        int k0 = (kt)*BK;                                                      \
        _Pragma("unroll")                                                      \
        for (int i = 0; i < 4; i++) {                                          \
            int f = tid + i*256; int row = f>>3, c4 = f&7;                     \
            cp16(&Asd[row*SA + c4*4], &A[(size_t)(bm+row)*K + k0 + c4*4]);     \
        }                                                                      \
        _Pragma("unroll")                                                      \
        for (int i = 0; i < 2; i++) {                                          \
            int f = tid + i*256; int kk = f>>4, n4 = f&15;                     \
            cp16(&Bsd[kk*SB + n4*4], &B[(size_t)(k0+kk)*N + bn + n4*4]);       \
        }                                                                      \
        CP_COMMIT();                                                           \
    }

    ISSUE(0);
    for (int kt = 0; kt < NK; kt++) {
        if (kt + 1 < NK) { ISSUE(kt+1); CP_WAIT(1); }
        else             { CP_WAIT(0); }
        __syncthreads();
        const unsigned* As = (const unsigned*)(smem + (kt&1)*AS_STG);
        const unsigned* Bs = (const unsigned*)(smem + 2*AS_STG + (kt&1)*BS_STG);
        #pragma unroll
        for (int ks = 0; ks < 4; ks++) {
            unsigned a[2][4], b[4][2];
            #pragma unroll
            for (int mt = 0; mt < 2; mt++) {
                int m0 = wm*32 + mt*16;
                const unsigned* ap = &As[(m0+g)*SA + ks*8 + t];
                a[mt][0]=ap[0]; a[mt][1]=ap[8*SA]; a[mt][2]=ap[4]; a[mt][3]=ap[8*SA+4];
            }
            #pragma unroll
            for (int nt = 0; nt < 4; nt++) {
                int n0 = wn*32 + nt*8;
                const unsigned* bp = &Bs[(ks*8+t)*SB + n0 + g];
                b[nt][0]=bp[0]; b[nt][1]=bp[4*SB];
            }
            #pragma unroll
            for (int mt = 0; mt < 2; mt++)
                #pragma unroll
                for (int nt = 0; nt < 4; nt++)
                    mma_tf32(acc[mt][nt], a[mt][0],a[mt][1],a[mt][2],a[mt][3],
                             b[nt][0], b[nt][1]);
        }
        __syncthreads();
    }
    #undef ISSUE

    #pragma unroll
    for (int mt = 0; mt < 2; mt++) {
        int r0 = bm + wm*32 + mt*16 + g;
        #pragma unroll
        for (int nt = 0; nt < 4; nt++) {
            int col = bn + wn*32 + nt*8 + 2*t;
            float bx = 0.f, by = 0.f;
            if (BIAS) { bx = bias[col]; by = bias[col+1]; }
            float2 o0, o1;
            o0.x = acc[mt][nt][0] + bx; o0.y = acc[mt][nt][1] + by;
            o1.x = acc[mt][nt][2] + bx; o1.y = acc[mt][nt][3] + by;
            if (RELU) {
                o0.x=fmaxf(o0.x,0.f); o0.y=fmaxf(o0.y,0.f);
                o1.x=fmaxf(o1.x,0.f); o1.y=fmaxf(o1.y,0.f);
            }
            if (ROUND) {
                o0.x=roundtf(o0.x); o0.y=roundtf(o0.y);
                o1.x=roundtf(o1.x); o1.y=roundtf(o1.y);
            }
            *(float2*)&C[(size_t)r0*N + col]     = o0;
            *(float2*)&C[(size_t)(r0+8)*N + col] = o1;
        }
    }
}

template<bool RELU, bool BIAS, bool ROUND>
__global__ __launch_bounds__(256)
void tgemm_kernel(const float* __restrict__ A, const float* __restrict__ B,
                  const float* __restrict__ bias, float* __restrict__ C,
                  int M, int N, int K)
{
    extern __shared__ float smem[];
    gemm_core<RELU, BIAS, ROUND>(A, B, nullptr ? nullptr : bias, C, N, K,
                                 blockIdx.y * 128, blockIdx.x * 64, smem);
}

// Fused QKV: grid (24, 50). blockIdx.x>>3 selects weight/output; &7 selects N-tile.
__global__ __launch_bounds__(256)
void tgemm_qkv_kernel(const float* __restrict__ h,
                      const float* __restrict__ wq, const float* __restrict__ wk,
                      const float* __restrict__ wv,
                      float* __restrict__ q, float* __restrict__ k, float* __restrict__ v)
{
    extern __shared__ float smem[];
    int sel = blockIdx.x >> 3;
    const float* B = (sel == 0) ? wq : (sel == 1) ? wk : wv;
    float*       C = (sel == 0) ? q  : (sel == 1) ? k  : v;
    gemm_core<false, false, false>(h, B, nullptr, C, HH, HH,
                                   blockIdx.y * 128, (blockIdx.x & 7) * 64, smem);
}

// ---------------- per-batch Gram, grid (2, 64) ----------------
__global__ __launch_bounds__(256)
void gram_kernel(const float* __restrict__ q, const float* __restrict__ kmat,
                 float* __restrict__ G)
{
    const int SA=36, SB=36, BK=32;
    __shared__ unsigned As[128*SA];
    __shared__ unsigned Bs[64*SB];
    int b = blockIdx.y;
    int n0 = blockIdx.x * 64;
    int tid = threadIdx.x, lane = tid & 31, w = tid >> 5;
    int wm = w & 3, wn = w >> 2;
    int g = lane >> 2, t = lane & 3;
    const float* qbp = q    + (size_t)b*SS*HH;
    const float* kbp = kmat + (size_t)b*SS*HH;

    float4 ar[4], br[2];
    float acc[2][4][4] = {};
    const int NK = HH / BK;

    #define LOADG(k0) {                                                        \
        _Pragma("unroll")                                                      \
        for (int i = 0; i < 4; i++) {                                          \
            int f = tid + i*256; int row = f>>3, c4 = (f&7)*4;                 \
            int sr = row < SS ? row : SS-1;                                    \
            ar[i] = *(const float4*)&qbp[(size_t)sr*HH + (k0) + c4];           \
        }                                                                      \
        _Pragma("unroll")                                                      \
        for (int i = 0; i < 2; i++) {                                          \
            int f = tid + i*256; int u = f>>3, c4 = (f&7)*4;                   \
            int su = (n0+u) < SS ? (n0+u) : SS-1;                              \
            br[i] = *(const float4*)&kbp[(size_t)su*HH + (k0) + c4];           \
        }                                                                      \
    }
    #define STORES() {                                                         \
        _Pragma("unroll")                                                      \
        for (int i = 0; i < 4; i++) {                                          \
            int f = tid + i*256; int row = f>>3, c4 = (f&7)*4;                 \
            int base = (c4>>3)*8 + (((c4&7)==4) ? 1 : 0);                      \
            unsigned* d = &As[row*SA + base];                                  \
            d[0]=f2tf(ar[i].x); d[2]=f2tf(ar[i].y);                            \
            d[4]=f2tf(ar[i].z); d[6]=f2tf(ar[i].w);                            \
        }                                                                      \
        _Pragma("unroll")                                                      \
        for (int i = 0; i < 2; i++) {                                          \
            int f = tid + i*256; int u = f>>3, c4 = (f&7)*4;                   \
            int base = (c4>>3)*8 + (((c4&7)==4) ? 1 : 0);                      \
            unsigned* d = &Bs[u*SB + base];                                    \
            d[0]=f2tf(br[i].x); d[2]=f2tf(br[i].y);                            \
            d[4]=f2tf(br[i].z); d[6]=f2tf(br[i].w);                            \
        }                                                                      \
    }

    LOADG(0); STORES(); __syncthreads();

    for (int kt = 0; kt < NK; kt++) {
        if (kt + 1 < NK) LOADG((kt+1)*BK);
        #pragma unroll
        for (int ks = 0; ks < 4; ks++) {
            unsigned a[2][4], bfr[4][2];
            #pragma unroll
            for (int mt = 0; mt < 2; mt++) {
                int r = wm*32 + mt*16 + g;
                uint2 lo = *(const uint2*)&As[r*SA + ks*8 + 2*t];
                uint2 hi = *(const uint2*)&As[(r+8)*SA + ks*8 + 2*t];
                a[mt][0]=lo.x; a[mt][1]=hi.x; a[mt][2]=lo.y; a[mt][3]=hi.y;
            }
            #pragma unroll
            for (int nt = 0; nt < 4; nt++) {
                int n = wn*32 + nt*8 + g;
                uint2 bb = *(const uint2*)&Bs[n*SB + ks*8 + 2*t];
                bfr[nt][0]=bb.x; bfr[nt][1]=bb.y;
            }
            #pragma unroll
            for (int mt = 0; mt < 2; mt++)
                #pragma unroll
                for (int nt = 0; nt < 4; nt++)
                    mma_tf32(acc[mt][nt], a[mt][0],a[mt][1],a[mt][2],a[mt][3],
                             bfr[nt][0], bfr[nt][1]);
        }
        __syncthreads();
        if (kt + 1 < NK) { STORES(); __syncthreads(); }
    }
    #undef LOADG
    #undef STORES

    const float invs = 0.044194173824159216f;  // 1/sqrt(512)
    float* Gb = G + (size_t)b*SS*SS;
    #pragma unroll
    for (int mt = 0; mt < 2; mt++) {
        int r0 = wm*32 + mt*16 + g;
        #pragma unroll
        for (int nt = 0; nt < 4; nt++) {
            int col = n0 + wn*32 + nt*8 + 2*t;
            if (col + 1 < SS) {
                if (r0 < SS) {
                    Gb[r0*SS + col]     = acc[mt][nt][0]*invs;
                    Gb[r0*SS + col + 1] = acc[mt][nt][1]*invs;
                }
                if (r0 + 8 < SS) {
                    Gb[(r0+8)*SS + col]     = acc[mt][nt][2]*invs;
                    Gb[(r0+8)*SS + col + 1] = acc[mt][nt][3]*invs;
                }
            } else if (col < SS) {
                if (r0 < SS)     Gb[r0*SS + col]     = acc[mt][nt][0]*invs;
                if (r0 + 8 < SS) Gb[(r0+8)*SS + col] = acc[mt][nt][2]*invs;
            }
        }
    }
}

// ---------------- softmax + beta + weighted V ----------------
__global__ __launch_bounds__(256)
void attn_kernel(const float* __restrict__ G, const float* __restrict__ v,
                 float* __restrict__ alpha_out, float* __restrict__ att)
{
    int blk = blockIdx.x;
    int b  = blk / (SS / STILE);
    int s0 = (blk % (SS / STILE)) * STILE;
    __shared__ float dmat[STILE][WIN * WIN];
    __shared__ float beta[STILE][WIN];
    const float* Gb = G + (size_t)b*SS*SS;
    int tid = threadIdx.x;

    for (int idx = tid; idx < STILE*WIN*WIN; idx += 256) {
        int si = idx / (WIN*WIN), r = idx % (WIN*WIN);
        int w_ = r / WIN, u = r % WIN;
        int s = s0 + si;
        int p  = s + WR - w_;
        int pu = s + WR - u;
        float val = 0.f;
        if (p >= 0 && p < SS && pu >= 0 && pu < SS)
            val = Gb[p*SS + pu];
        dmat[si][r] = val;
    }
    __syncthreads();

    int warp = tid >> 5, lane = tid & 31;
    for (int rr = warp; rr < STILE*WIN; rr += 8) {
        int si = rr / WIN, r = rr % WIN;
        float* row = &dmat[si][r*WIN];
        float x0 = row[lane];
        float x1 = (lane == 0) ? row[32] : -1e30f;
        float m = fmaxf(x0, x1);
#pragma unroll
        for (int o = 16; o; o >>= 1)
            m = fmaxf(m, __shfl_xor_sync(0xffffffffu, m, o));
        float e0 = __expf(x0 - m);
        float e1 = (lane == 0) ? __expf(x1 - m) : 0.f;
        float ssum = e0 + e1;
#pragma unroll
        for (int o = 16; o; o >>= 1)
            ssum += __shfl_xor_sync(0xffffffffu, ssum, o);
        float rinv = __frcp_rn(ssum);
        e0 *= rinv; e1 *= rinv;
        row[lane] = e0;
        if (lane == 0) row[32] = e1;
        float* ao = alpha_out + (size_t)(b*SS + s0 + si)*(WIN*WIN) + r*WIN;
        ao[lane] = e0;
        if (lane == 0) ao[32] = e1;
    }
    __syncthreads();

    for (int idx = tid; idx < STILE*WIN; idx += 256) {
        int si = idx / WIN, u = idx % WIN;
        float acc = 0.f;
        for (int r = 0; r < WIN; r++) acc += dmat[si][r*WIN + u];
        beta[si][u] = acc;
    }
    __syncthreads();

    int h2 = tid * 2;
    float2 acc[STILE];
#pragma unroll
    for (int si = 0; si < STILE; si++) { acc[si].x = 0.f; acc[si].y = 0.f; }

#pragma unroll
    for (int j = 0; j < STILE - 1 + 2*WR + 1; j++) {
        int p = s0 - WR + j;
        if (p >= 0 && p < SS) {
            float2 vr = *(const float2*)&v[(size_t)(b*SS + p)*HH + h2];
#pragma unroll
            for (int si = 0; si < STILE; si++) {
                int u = si + 2*WR - j;
                if (u >= 0 && u < WIN) {
                    float bu = beta[si][u];
                    acc[si].x = fmaf(bu, vr.x, acc[si].x);
                    acc[si].y = fmaf(bu, vr.y, acc[si].y);
                }
            }
        }
    }
#pragma unroll
    for (int si = 0; si < STILE; si++) {
        float2 o;
        o.x = roundtf(acc[si].x);   // att feeds the final tf32 GEMM
        o.y = roundtf(acc[si].y);
        *(float2*)&att[(size_t)(b*SS + s0 + si)*HH + h2] = o;
    }
}

// ---------------- launch ----------------
extern "C" void kernel_launch(void* const* d_in, const int* in_sizes, int n_in,
                              void* d_out, int out_size)
{
    const float* x  = (const float*)d_in[0];
    const float* W0 = (const float*)d_in[1];
    const float* b0 = (const float*)d_in[2];
    const float* Wq = (const float*)d_in[3];
    const float* Wk = (const float*)d_in[4];
    const float* Wv = (const float*)d_in[5];
    const float* W1 = (const float*)d_in[6];
    const float* b1 = (const float*)d_in[7];
    float* out = (float*)d_out;
    float* y_out     = out;
    float* alpha_out = out + (size_t)NBS * DOUT;

    float *xr,*w0r,*wqr,*wkr,*wvr,*w1r,*h,*q,*k,*v,*G,*att;
    cudaGetSymbolAddress((void**)&xr,  g_x);
    cudaGetSymbolAddress((void**)&w0r, g_w0);
    cudaGetSymbolAddress((void**)&wqr, g_wq);
    cudaGetSymbolAddress((void**)&wkr, g_wk);
    cudaGetSymbolAddress((void**)&wvr, g_wv);
    cudaGetSymbolAddress((void**)&w1r, g_w1);
    cudaGetSymbolAddress((void**)&h,   g_h);
    cudaGetSymbolAddress((void**)&q,   g_q);
    cudaGetSymbolAddress((void**)&k,   g_k);
    cudaGetSymbolAddress((void**)&v,   g_v);
    cudaGetSymbolAddress((void**)&G,   g_G);
    cudaGetSymbolAddress((void**)&att, g_att);

    cudaFuncSetAttribute(tgemm_kernel<true,  true,  true >, cudaFuncAttributeMaxDynamicSharedMemorySize, SMEM_GEMM);
    cudaFuncSetAttribute(tgemm_kernel<true,  true,  false>, cudaFuncAttributeMaxDynamicSharedMemorySize, SMEM_GEMM);
    cudaFuncSetAttribute(tgemm_qkv_kernel, cudaFuncAttributeMaxDynamicSharedMemorySize, SMEM_GEMM);

    // tf32 rounding: x (1600 blocks) + all weights fused (1024 blocks)
    roundtf_kernel<<<(NBS*DIN/4 + 255)/256, 256>>>(x, xr, NBS*DIN/4);
    round_weights_kernel<<<1024, 256>>>(W0, Wq, Wk, Wv, W1, w0r, wqr, wkr, wvr, w1r);

    // h = relu(x@W0 + b0), output tf32-rounded (feeds QKV)
    tgemm_kernel<true, true, true><<<dim3(HH/64, NBS/128), 256, SMEM_GEMM>>>(
        xr, w0r, b0, h, NBS, HH, DIN);
    // fused q,k,v
    tgemm_qkv_kernel<<<dim3(24, NBS/128), 256, SMEM_GEMM>>>(h, wqr, wkr, wvr, q, k, v);
    // Gram + attention
    gram_kernel<<<dim3(2, BB), 256>>>(q, k, G);
    attn_kernel<<<NBS/STILE, 256>>>(G, v, alpha_out, att);
    // y = relu(att@W1 + b1)
    tgemm_kernel<true, true, false><<<dim3(DOUT/64, NBS/128), 256, SMEM_GEMM>>>(
        att, w1r, b1, y_out, NBS, DOUT, HH);
}